// round 15
// baseline (speedup 1.0000x reference)
#include <cuda_runtime.h>
#include <cuda_fp16.h>
#include <cstdint>

#define HIDDEN 768
#define META 25
#define NMENT 2000
#define NPAIRS 40000
#define BATCH 2
#define MROWS (BATCH * NMENT)     // 4000
#define MPAD 4096
#define NCOLS (2 * HIDDEN)        // 1536
#define EDC 300
#define TOTPAIRS (BATCH * NPAIRS) // 80000

// -------------------- scratch (static device globals) ----------------------
__device__ __half g_Ph[MROWS * NCOLS];        // 12.3 MB  P in fp16
__device__ __half g_Eh[EDC * HIDDEN];         // 0.46 MB  E in fp16
__device__ __half g_Ah[MPAD * HIDDEN];        // fp16 mentions (padded)
__device__ __half g_Wt[NCOLS * HIDDEN];       // W^T packed, fp16

// ---------------------------------------------------------------------------
// Fused prep: [0, NBA)          convert A -> fp16, 8 elems/thread (vectorized)
//             [NBA, NBA+NBW)    transpose+convert W -> g_Wt
//             [NBA+NBW, ...)    E = ed_table @ W1c + b1 -> fp16
// ---------------------------------------------------------------------------
#define NBA (MPAD * HIDDEN / (256 * 8))        // 1536
#define NBW ((HIDDEN / 32) * (NCOLS / 32))     // 1152
#define NBE ((EDC * HIDDEN + 255) / 256)       // 900
#define NB_PREP (NBA + NBW + NBE)

__global__ __launch_bounds__(256) void prep_kernel(
    const float* __restrict__ M, const float* __restrict__ W1,
    const float* __restrict__ ed_table, const float* __restrict__ b1)
{
    __shared__ float t[32][33];
    const int bid = blockIdx.x;
    const int tid = threadIdx.x;

    if (bid < NBA) {
        const int base = (bid * 256 + tid) * 8;
        const int row = base / HIDDEN;
        uint4 outv;
        if (row < MROWS) {
            float4 v0 = *(const float4*)(M + base);
            float4 v1 = *(const float4*)(M + base + 4);
            __half2* h = (__half2*)&outv;
            h[0] = __floats2half2_rn(v0.x, v0.y);
            h[1] = __floats2half2_rn(v0.z, v0.w);
            h[2] = __floats2half2_rn(v1.x, v1.y);
            h[3] = __floats2half2_rn(v1.z, v1.w);
        } else {
            outv = make_uint4(0, 0, 0, 0);
        }
        *(uint4*)(g_Ah + base) = outv;
    } else if (bid < NBA + NBW) {
        const int bw = bid - NBA;
        const int kt = (bw % (HIDDEN / 32)) * 32;
        const int nt = (bw / (HIDDEN / 32)) * 32;
        const int x = tid & 31;
        const int y = tid >> 5;            // 0..7
        const int srcRowBase = (nt < HIDDEN) ? 0 : HIDDEN;
        const int srcCol     = ((nt < HIDDEN) ? nt : nt - HIDDEN) + x;
        #pragma unroll
        for (int r = y; r < 32; r += 8)
            t[r][x] = W1[(size_t)(srcRowBase + kt + r) * HIDDEN + srcCol];
        __syncthreads();
        #pragma unroll
        for (int r = y; r < 32; r += 8)
            g_Wt[(size_t)(nt + r) * HIDDEN + kt + x] = __float2half(t[x][r]);
    } else {
        int idx = (bid - NBA - NBW) * 256 + tid;
        if (idx < EDC * HIDDEN) {
            int e = idx / HIDDEN;
            int j = idx % HIDDEN;
            float s = b1[j];
            #pragma unroll
            for (int tt = 0; tt < META; tt++)
                s += ed_table[e * META + tt] * W1[(size_t)(2 * HIDDEN + tt) * HIDDEN + j];
            g_Eh[idx] = __float2half(s);
        }
    }
}

// ---------------------------------------------------------------------------
// fp16 mma.sync GEMM: P = A @ Wt^T, fp32 accum, fp16 store.
// R9 mainloop, but 3 cp.async stages + __launch_bounds__(256,3):
// 60KB smem/CTA and <=85 regs -> 3 CTA/SM -> grid 384 < n_conc 444
// -> SINGLE WAVE, 6 warps/SMSP.
// ---------------------------------------------------------------------------
#define BK 32
#define NBLK (HIDDEN / BK)          // 24
#define ROWB 80
#define TILEB (128 * ROWB)          // 10240
#define STAGEB (2 * TILEB)          // 20480 (A, B)
#define STAGES 3
#define GEMM_SMEM (STAGES * STAGEB) // 61440

static __device__ __forceinline__ uint32_t smem_u32(const void* p) {
    uint32_t a;
    asm("{ .reg .u64 t; cvta.to.shared.u64 t, %1; cvt.u32.u64 %0, t; }" : "=r"(a) : "l"(p));
    return a;
}
static __device__ __forceinline__ void cp16(uint32_t dst, const void* src) {
    asm volatile("cp.async.cg.shared.global [%0], [%1], 16;" :: "r"(dst), "l"(src));
}
static __device__ __forceinline__ void ldmx4(uint32_t& r0, uint32_t& r1,
                                             uint32_t& r2, uint32_t& r3, uint32_t a) {
    asm volatile("ldmatrix.sync.aligned.m8n8.x4.shared.b16 {%0,%1,%2,%3}, [%4];"
                 : "=r"(r0), "=r"(r1), "=r"(r2), "=r"(r3) : "r"(a));
}
static __device__ __forceinline__ void mma16816(float* c, const uint32_t* a, const uint32_t* b) {
    asm volatile(
        "mma.sync.aligned.m16n8k16.row.col.f32.f16.f16.f32 "
        "{%0,%1,%2,%3}, {%4,%5,%6,%7}, {%8,%9}, {%0,%1,%2,%3};"
        : "+f"(c[0]), "+f"(c[1]), "+f"(c[2]), "+f"(c[3])
        : "r"(a[0]), "r"(a[1]), "r"(a[2]), "r"(a[3]), "r"(b[0]), "r"(b[1]));
}

__global__ __launch_bounds__(256, 3) void mma_gemm_kernel() {
    extern __shared__ char smem[];
    const uint32_t sb = smem_u32(smem);
    const int tid = threadIdx.x;
    const int lane = tid & 31;
    const int wid = tid >> 5;
    const int m0 = blockIdx.y * 128;
    const int n0 = blockIdx.x * 128;
    const int warpM = wid & 1;       // 2 warps in M
    const int warpN = wid >> 1;      // 4 warps in N

    const int ldRow = tid >> 1;      // 0..127
    const int ldSeg = (tid & 1) * 2; // 0 or 2 (16B segs)

    float acc[4][4][4];
    #pragma unroll
    for (int i = 0; i < 4; i++)
        #pragma unroll
        for (int j = 0; j < 4; j++)
            #pragma unroll
            for (int q = 0; q < 4; q++) acc[i][j][q] = 0.f;

    auto issue_load = [&](int blk) {
        const int stage = blk % STAGES;
        const __half* ga = g_Ah + (size_t)(m0 + ldRow) * HIDDEN + blk * BK + ldSeg * 8;
        const __half* gb = g_Wt + (size_t)(n0 + ldRow) * HIDDEN + blk * BK + ldSeg * 8;
        uint32_t d = sb + stage * STAGEB + ldRow * ROWB + ldSeg * 16;
        cp16(d,         ga);  cp16(d + 16,         ga + 8);
        cp16(d + TILEB, gb);  cp16(d + TILEB + 16, gb + 8);
        asm volatile("cp.async.commit_group;" ::: "memory");
    };

    issue_load(0);
    issue_load(1);

    // precomputed intra-tile ldmatrix offsets
    const uint32_t aoff = (warpM * 64 + (lane & 15)) * ROWB + (lane >> 4) * 16;
    const int gg = lane >> 3;
    const int rr = lane & 7;
    const uint32_t boff = (warpN * 32 + ((gg >> 1) * 8 + rr)) * ROWB + (gg & 1) * 16;

    for (int blk = 0; blk < NBLK; blk++) {
        const int stage = blk % STAGES;
        asm volatile("cp.async.wait_group 1;" ::: "memory");
        __syncthreads();
        if (blk + 2 < NBLK) issue_load(blk + 2);

        const uint32_t Ab = sb + stage * STAGEB;
        const uint32_t Bb = Ab + TILEB;

        // hoist ALL fragments for this k-block (2 x k16)
        uint32_t a[2][4][4], b[2][4][2];
        #pragma unroll
        for (int ks = 0; ks < 2; ks++) {
            const int kb = ks * 32;
            #pragma unroll
            for (int nf2 = 0; nf2 < 2; nf2++)
                ldmx4(b[ks][nf2 * 2][0], b[ks][nf2 * 2][1],
                      b[ks][nf2 * 2 + 1][0], b[ks][nf2 * 2 + 1][1],
                      Bb + boff + nf2 * 16 * ROWB + kb);
            #pragma unroll
            for (int mf = 0; mf < 4; mf++)
                ldmx4(a[ks][mf][0], a[ks][mf][1], a[ks][mf][2], a[ks][mf][3],
                      Ab + aoff + mf * 16 * ROWB + kb);
        }
        #pragma unroll
        for (int ks = 0; ks < 2; ks++)
            #pragma unroll
            for (int mf = 0; mf < 4; mf++)
                #pragma unroll
                for (int nf = 0; nf < 4; nf++)
                    mma16816(acc[mf][nf], a[ks][mf], b[ks][nf]);
    }

    // store P as fp16
    #pragma unroll
    for (int mf = 0; mf < 4; mf++) {
        const int r0 = m0 + warpM * 64 + mf * 16 + (lane >> 2);
        #pragma unroll
        for (int nf = 0; nf < 4; nf++) {
            const int c = n0 + warpN * 32 + nf * 8 + (lane & 3) * 2;
            if (r0 < MROWS)
                *(__half2*)(g_Ph + (size_t)r0 * NCOLS + c) =
                    __floats2half2_rn(acc[mf][nf][0], acc[mf][nf][1]);
            if (r0 + 8 < MROWS)
                *(__half2*)(g_Ph + (size_t)(r0 + 8) * NCOLS + c) =
                    __floats2half2_rn(acc[mf][nf][2], acc[mf][nf][3]);
        }
    }
}

// ---------------------------------------------------------------------------
// Epilogue: one warp per pair; P and E rows in fp16.  (At the LTS-cap
// roofline: 368MB / 12.3TB/s — do not touch.)
// ---------------------------------------------------------------------------
__global__ __launch_bounds__(256) void epilogue_kernel(
    const int* __restrict__ pairs, const int* __restrict__ eds,
    const float* __restrict__ W2, const float* __restrict__ b2,
    float* __restrict__ out)
{
    __shared__ float w2s[HIDDEN];
    const int tid = threadIdx.x;
    for (int i = tid; i < HIDDEN; i += 256) w2s[i] = W2[i];
    __syncthreads();

    const int warp = tid / 32;
    const int lane = tid % 32;
    const int p = blockIdx.x * 8 + warp;
    if (p >= TOTPAIRS) return;

    const int b  = p / NPAIRS;
    const int i0 = pairs[(size_t)p * 2 + 0];
    const int i1 = pairs[(size_t)p * 2 + 1];
    const int e  = eds[p];

    const __half* rowA = g_Ph + (size_t)(b * NMENT + i0) * NCOLS;
    const __half* rowB = g_Ph + (size_t)(b * NMENT + i1) * NCOLS + HIDDEN;
    const __half* rowE = g_Eh + (size_t)e * HIDDEN;

    float acc = 0.f;
    #pragma unroll
    for (int j0 = 0; j0 < 3; j0++) {
        const int h0 = j0 * 256 + lane * 8;   // half index, 16B aligned
        uint4 ua = *(const uint4*)(rowA + h0);
        uint4 ub = *(const uint4*)(rowB + h0);
        uint4 ue = *(const uint4*)(rowE + h0);
        const __half2* ha = (const __half2*)&ua;
        const __half2* hb = (const __half2*)&ub;
        const __half2* he = (const __half2*)&ue;
        #pragma unroll
        for (int q = 0; q < 4; q++) {
            float2 fa = __half22float2(ha[q]);
            float2 fb = __half22float2(hb[q]);
            float2 fe = __half22float2(he[q]);
            float2 fw = *(const float2*)(&w2s[h0 + q * 2]);
            float v;
            v = fa.x + fb.x + fe.x; acc += fmaxf(v, 0.f) * fw.x;
            v = fa.y + fb.y + fe.y; acc += fmaxf(v, 0.f) * fw.y;
        }
    }
    #pragma unroll
    for (int off = 16; off; off >>= 1)
        acc += __shfl_xor_sync(0xffffffff, acc, off);
    if (lane == 0) out[p] = acc + b2[0];
}

// ---------------------------------------------------------------------------
extern "C" void kernel_launch(void* const* d_in, const int* in_sizes, int n_in,
                              void* d_out, int out_size) {
    const float* mention_reprs = (const float*)d_in[0];
    const int*   pairs         = (const int*)d_in[1];
    const int*   eds           = (const int*)d_in[2];
    const float* ed_table      = (const float*)d_in[3];
    const float* W1            = (const float*)d_in[4];
    const float* b1            = (const float*)d_in[5];
    const float* W2            = (const float*)d_in[6];
    const float* b2            = (const float*)d_in[7];
    float* out = (float*)d_out;

    cudaFuncSetAttribute(mma_gemm_kernel,
                         cudaFuncAttributeMaxDynamicSharedMemorySize, GEMM_SMEM);

    prep_kernel<<<NB_PREP, 256>>>(mention_reprs, W1, ed_table, b1);
    { dim3 grid(NCOLS / 128, MPAD / 128);  // (12, 32)
      mma_gemm_kernel<<<grid, 256, GEMM_SMEM>>>(); }
    epilogue_kernel<<<(TOTPAIRS + 7) / 8, 256>>>(pairs, eds, W2, b2, out);
}

// round 16
// speedup vs baseline: 1.2299x; 1.2299x over previous
#include <cuda_runtime.h>
#include <cuda_fp16.h>
#include <cstdint>

#define HIDDEN 768
#define META 25
#define NMENT 2000
#define NPAIRS 40000
#define BATCH 2
#define MROWS (BATCH * NMENT)     // 4000
#define MPAD 4096
#define NCOLS (2 * HIDDEN)        // 1536
#define EDC 300
#define TOTPAIRS (BATCH * NPAIRS) // 80000

// -------------------- scratch (static device globals) ----------------------
__device__ __half g_Ph[MROWS * NCOLS];        // 12.3 MB  P in fp16
__device__ __half g_Eh[EDC * HIDDEN];         // 0.46 MB  E in fp16
__device__ __half g_Ah[MPAD * HIDDEN];        // fp16 mentions (padded)
__device__ __half g_Wt[NCOLS * HIDDEN];       // W^T packed, fp16

// ---------------------------------------------------------------------------
// Fused prep: [0, NBA)          convert A -> fp16, 8 elems/thread (vectorized)
//             [NBA, NBA+NBW)    transpose+convert W -> g_Wt
//             [NBA+NBW, ...)    E = ed_table @ W1c + b1 -> fp16
// ---------------------------------------------------------------------------
#define NBA (MPAD * HIDDEN / (256 * 8))        // 1536
#define NBW ((HIDDEN / 32) * (NCOLS / 32))     // 1152
#define NBE ((EDC * HIDDEN + 255) / 256)       // 900
#define NB_PREP (NBA + NBW + NBE)

__global__ __launch_bounds__(256) void prep_kernel(
    const float* __restrict__ M, const float* __restrict__ W1,
    const float* __restrict__ ed_table, const float* __restrict__ b1)
{
    __shared__ float t[32][33];
    const int bid = blockIdx.x;
    const int tid = threadIdx.x;

    if (bid < NBA) {
        const int base = (bid * 256 + tid) * 8;
        const int row = base / HIDDEN;
        uint4 outv;
        if (row < MROWS) {
            float4 v0 = *(const float4*)(M + base);
            float4 v1 = *(const float4*)(M + base + 4);
            __half2* h = (__half2*)&outv;
            h[0] = __floats2half2_rn(v0.x, v0.y);
            h[1] = __floats2half2_rn(v0.z, v0.w);
            h[2] = __floats2half2_rn(v1.x, v1.y);
            h[3] = __floats2half2_rn(v1.z, v1.w);
        } else {
            outv = make_uint4(0, 0, 0, 0);
        }
        *(uint4*)(g_Ah + base) = outv;
    } else if (bid < NBA + NBW) {
        const int bw = bid - NBA;
        const int kt = (bw % (HIDDEN / 32)) * 32;
        const int nt = (bw / (HIDDEN / 32)) * 32;
        const int x = tid & 31;
        const int y = tid >> 5;            // 0..7
        const int srcRowBase = (nt < HIDDEN) ? 0 : HIDDEN;
        const int srcCol     = ((nt < HIDDEN) ? nt : nt - HIDDEN) + x;
        #pragma unroll
        for (int r = y; r < 32; r += 8)
            t[r][x] = W1[(size_t)(srcRowBase + kt + r) * HIDDEN + srcCol];
        __syncthreads();
        #pragma unroll
        for (int r = y; r < 32; r += 8)
            g_Wt[(size_t)(nt + r) * HIDDEN + kt + x] = __float2half(t[x][r]);
    } else {
        int idx = (bid - NBA - NBW) * 256 + tid;
        if (idx < EDC * HIDDEN) {
            int e = idx / HIDDEN;
            int j = idx % HIDDEN;
            float s = b1[j];
            #pragma unroll
            for (int tt = 0; tt < META; tt++)
                s += ed_table[e * META + tt] * W1[(size_t)(2 * HIDDEN + tt) * HIDDEN + j];
            g_Eh[idx] = __float2half(s);
        }
    }
}

// ---------------------------------------------------------------------------
// fp16 mma.sync GEMM: P = A @ Wt^T, fp32 accum, fp16 store.
// R9 config (128x128, BK=32, 20KB stages, 4-stage ring, 256 thr, 2 CTA/SM)
// but TWO k-blocks per barrier: pair-wise wait/sync/issue. 12 syncs vs 24.
// ---------------------------------------------------------------------------
#define BK 32
#define NBLK (HIDDEN / BK)          // 24
#define NPAIR (NBLK / 2)            // 12
#define ROWB 80
#define TILEB (128 * ROWB)          // 10240
#define STAGEB (2 * TILEB)          // 20480 (A, B)
#define STAGES 4
#define GEMM_SMEM (STAGES * STAGEB) // 81920

static __device__ __forceinline__ uint32_t smem_u32(const void* p) {
    uint32_t a;
    asm("{ .reg .u64 t; cvta.to.shared.u64 t, %1; cvt.u32.u64 %0, t; }" : "=r"(a) : "l"(p));
    return a;
}
static __device__ __forceinline__ void cp16(uint32_t dst, const void* src) {
    asm volatile("cp.async.cg.shared.global [%0], [%1], 16;" :: "r"(dst), "l"(src));
}
static __device__ __forceinline__ void ldmx4(uint32_t& r0, uint32_t& r1,
                                             uint32_t& r2, uint32_t& r3, uint32_t a) {
    asm volatile("ldmatrix.sync.aligned.m8n8.x4.shared.b16 {%0,%1,%2,%3}, [%4];"
                 : "=r"(r0), "=r"(r1), "=r"(r2), "=r"(r3) : "r"(a));
}
static __device__ __forceinline__ void mma16816(float* c, const uint32_t* a, const uint32_t* b) {
    asm volatile(
        "mma.sync.aligned.m16n8k16.row.col.f32.f16.f16.f32 "
        "{%0,%1,%2,%3}, {%4,%5,%6,%7}, {%8,%9}, {%0,%1,%2,%3};"
        : "+f"(c[0]), "+f"(c[1]), "+f"(c[2]), "+f"(c[3])
        : "r"(a[0]), "r"(a[1]), "r"(a[2]), "r"(a[3]), "r"(b[0]), "r"(b[1]));
}

__global__ __launch_bounds__(256, 2) void mma_gemm_kernel() {
    extern __shared__ char smem[];
    const uint32_t sb = smem_u32(smem);
    const int tid = threadIdx.x;
    const int lane = tid & 31;
    const int wid = tid >> 5;
    const int m0 = blockIdx.y * 128;
    const int n0 = blockIdx.x * 128;
    const int warpM = wid & 1;       // 2 warps in M
    const int warpN = wid >> 1;      // 4 warps in N

    const int ldRow = tid >> 1;      // 0..127
    const int ldSeg = (tid & 1) * 2; // 0 or 2 (16B segs)

    float acc[4][4][4];
    #pragma unroll
    for (int i = 0; i < 4; i++)
        #pragma unroll
        for (int j = 0; j < 4; j++)
            #pragma unroll
            for (int q = 0; q < 4; q++) acc[i][j][q] = 0.f;

    // load ONE k-block into its stage (no commit)
    auto issue_block = [&](int blk) {
        const int stage = blk % STAGES;
        const __half* ga = g_Ah + (size_t)(m0 + ldRow) * HIDDEN + blk * BK + ldSeg * 8;
        const __half* gb = g_Wt + (size_t)(n0 + ldRow) * HIDDEN + blk * BK + ldSeg * 8;
        uint32_t d = sb + stage * STAGEB + ldRow * ROWB + ldSeg * 16;
        cp16(d,         ga);  cp16(d + 16,         ga + 8);
        cp16(d + TILEB, gb);  cp16(d + TILEB + 16, gb + 8);
    };
    // issue a PAIR of k-blocks as one commit group
    auto issue_pair = [&](int pb) {
        issue_block(2 * pb);
        issue_block(2 * pb + 1);
        asm volatile("cp.async.commit_group;" ::: "memory");
    };

    // precomputed intra-tile ldmatrix offsets
    const uint32_t aoff = (warpM * 64 + (lane & 15)) * ROWB + (lane >> 4) * 16;
    const int gg = lane >> 3;
    const int rr = lane & 7;
    const uint32_t boff = (warpN * 32 + ((gg >> 1) * 8 + rr)) * ROWB + (gg & 1) * 16;

    // proven R7/R9 per-block body: hoist 12 LDSM then 32 HMMA
    auto compute_block = [&](int blk) {
        const uint32_t Ab = sb + (blk % STAGES) * STAGEB;
        const uint32_t Bb = Ab + TILEB;
        uint32_t a[2][4][4], b[2][4][2];
        #pragma unroll
        for (int ks = 0; ks < 2; ks++) {
            const int kb = ks * 32;
            #pragma unroll
            for (int nf2 = 0; nf2 < 2; nf2++)
                ldmx4(b[ks][nf2 * 2][0], b[ks][nf2 * 2][1],
                      b[ks][nf2 * 2 + 1][0], b[ks][nf2 * 2 + 1][1],
                      Bb + boff + nf2 * 16 * ROWB + kb);
            #pragma unroll
            for (int mf = 0; mf < 4; mf++)
                ldmx4(a[ks][mf][0], a[ks][mf][1], a[ks][mf][2], a[ks][mf][3],
                      Ab + aoff + mf * 16 * ROWB + kb);
        }
        #pragma unroll
        for (int ks = 0; ks < 2; ks++)
            #pragma unroll
            for (int mf = 0; mf < 4; mf++)
                #pragma unroll
                for (int nf = 0; nf < 4; nf++)
                    mma16816(acc[mf][nf], a[ks][mf], b[ks][nf]);
    };

    // prologue: pair 0 in flight
    issue_pair(0);

    for (int pb = 0; pb < NPAIR; pb++) {
        // drain the pair we're about to read (only outstanding group)
        asm volatile("cp.async.wait_group 0;" ::: "memory");
        __syncthreads();
        // issue next pair into the other two stages (disjoint mod 4);
        // overlaps with this pair's 24 LDSM + 64 HMMA
        if (pb + 1 < NPAIR) issue_pair(pb + 1);

        compute_block(2 * pb);
        compute_block(2 * pb + 1);
    }

    // store P as fp16
    #pragma unroll
    for (int mf = 0; mf < 4; mf++) {
        const int r0 = m0 + warpM * 64 + mf * 16 + (lane >> 2);
        #pragma unroll
        for (int nf = 0; nf < 4; nf++) {
            const int c = n0 + warpN * 32 + nf * 8 + (lane & 3) * 2;
            if (r0 < MROWS)
                *(__half2*)(g_Ph + (size_t)r0 * NCOLS + c) =
                    __floats2half2_rn(acc[mf][nf][0], acc[mf][nf][1]);
            if (r0 + 8 < MROWS)
                *(__half2*)(g_Ph + (size_t)(r0 + 8) * NCOLS + c) =
                    __floats2half2_rn(acc[mf][nf][2], acc[mf][nf][3]);
        }
    }
}

// ---------------------------------------------------------------------------
// Epilogue: one warp per pair; P and E rows in fp16.  (At the LTS-cap
// roofline: 368MB / 12.3TB/s — do not touch.)
// ---------------------------------------------------------------------------
__global__ __launch_bounds__(256) void epilogue_kernel(
    const int* __restrict__ pairs, const int* __restrict__ eds,
    const float* __restrict__ W2, const float* __restrict__ b2,
    float* __restrict__ out)
{
    __shared__ float w2s[HIDDEN];
    const int tid = threadIdx.x;
    for (int i = tid; i < HIDDEN; i += 256) w2s[i] = W2[i];
    __syncthreads();

    const int warp = tid / 32;
    const int lane = tid % 32;
    const int p = blockIdx.x * 8 + warp;
    if (p >= TOTPAIRS) return;

    const int b  = p / NPAIRS;
    const int i0 = pairs[(size_t)p * 2 + 0];
    const int i1 = pairs[(size_t)p * 2 + 1];
    const int e  = eds[p];

    const __half* rowA = g_Ph + (size_t)(b * NMENT + i0) * NCOLS;
    const __half* rowB = g_Ph + (size_t)(b * NMENT + i1) * NCOLS + HIDDEN;
    const __half* rowE = g_Eh + (size_t)e * HIDDEN;

    float acc = 0.f;
    #pragma unroll
    for (int j0 = 0; j0 < 3; j0++) {
        const int h0 = j0 * 256 + lane * 8;   // half index, 16B aligned
        uint4 ua = *(const uint4*)(rowA + h0);
        uint4 ub = *(const uint4*)(rowB + h0);
        uint4 ue = *(const uint4*)(rowE + h0);
        const __half2* ha = (const __half2*)&ua;
        const __half2* hb = (const __half2*)&ub;
        const __half2* he = (const __half2*)&ue;
        #pragma unroll
        for (int q = 0; q < 4; q++) {
            float2 fa = __half22float2(ha[q]);
            float2 fb = __half22float2(hb[q]);
            float2 fe = __half22float2(he[q]);
            float2 fw = *(const float2*)(&w2s[h0 + q * 2]);
            float v;
            v = fa.x + fb.x + fe.x; acc += fmaxf(v, 0.f) * fw.x;
            v = fa.y + fb.y + fe.y; acc += fmaxf(v, 0.f) * fw.y;
        }
    }
    #pragma unroll
    for (int off = 16; off; off >>= 1)
        acc += __shfl_xor_sync(0xffffffff, acc, off);
    if (lane == 0) out[p] = acc + b2[0];
}

// ---------------------------------------------------------------------------
extern "C" void kernel_launch(void* const* d_in, const int* in_sizes, int n_in,
                              void* d_out, int out_size) {
    const float* mention_reprs = (const float*)d_in[0];
    const int*   pairs         = (const int*)d_in[1];
    const int*   eds           = (const int*)d_in[2];
    const float* ed_table      = (const float*)d_in[3];
    const float* W1            = (const float*)d_in[4];
    const float* b1            = (const float*)d_in[5];
    const float* W2            = (const float*)d_in[6];
    const float* b2            = (const float*)d_in[7];
    float* out = (float*)d_out;

    cudaFuncSetAttribute(mma_gemm_kernel,
                         cudaFuncAttributeMaxDynamicSharedMemorySize, GEMM_SMEM);

    prep_kernel<<<NB_PREP, 256>>>(mention_reprs, W1, ed_table, b1);
    { dim3 grid(NCOLS / 128, MPAD / 128);  // (12, 32)
      mma_gemm_kernel<<<grid, 256, GEMM_SMEM>>>(); }
    epilogue_kernel<<<(TOTPAIRS + 7) / 8, 256>>>(pairs, eds, W2, b2, out);
}

// round 17
// speedup vs baseline: 1.4194x; 1.1541x over previous
#include <cuda_runtime.h>
#include <cuda_fp16.h>
#include <cstdint>

#define HIDDEN 768
#define META 25
#define NMENT 2000
#define NPAIRS 40000
#define BATCH 2
#define MROWS (BATCH * NMENT)     // 4000
#define MPAD 4096
#define NCOLS (2 * HIDDEN)        // 1536
#define EDC 300
#define TOTPAIRS (BATCH * NPAIRS) // 80000

// -------------------- scratch (static device globals) ----------------------
__device__ __half g_Ph[MROWS * NCOLS];        // 12.3 MB  P in fp16
__device__ __half g_Eh[EDC * HIDDEN];         // 0.46 MB  E in fp16
__device__ __half g_Ah[MPAD * HIDDEN];        // fp16 mentions (padded)
__device__ __half g_Wt[NCOLS * HIDDEN];       // W^T packed, fp16

// ---------------------------------------------------------------------------
// Fused prep: [0, NBA)          convert A -> fp16, 8 elems/thread (vectorized)
//             [NBA, NBA+NBW)    transpose+convert W -> g_Wt
//             [NBA+NBW, ...)    E = ed_table @ W1c + b1 -> fp16
// ---------------------------------------------------------------------------
#define NBA (MPAD * HIDDEN / (256 * 8))        // 1536
#define NBW ((HIDDEN / 32) * (NCOLS / 32))     // 1152
#define NBE ((EDC * HIDDEN + 255) / 256)       // 900
#define NB_PREP (NBA + NBW + NBE)

__global__ __launch_bounds__(256) void prep_kernel(
    const float* __restrict__ M, const float* __restrict__ W1,
    const float* __restrict__ ed_table, const float* __restrict__ b1)
{
    __shared__ float t[32][33];
    const int bid = blockIdx.x;
    const int tid = threadIdx.x;

    if (bid < NBA) {
        const int base = (bid * 256 + tid) * 8;
        const int row = base / HIDDEN;
        uint4 outv;
        if (row < MROWS) {
            float4 v0 = *(const float4*)(M + base);
            float4 v1 = *(const float4*)(M + base + 4);
            __half2* h = (__half2*)&outv;
            h[0] = __floats2half2_rn(v0.x, v0.y);
            h[1] = __floats2half2_rn(v0.z, v0.w);
            h[2] = __floats2half2_rn(v1.x, v1.y);
            h[3] = __floats2half2_rn(v1.z, v1.w);
        } else {
            outv = make_uint4(0, 0, 0, 0);
        }
        *(uint4*)(g_Ah + base) = outv;
    } else if (bid < NBA + NBW) {
        const int bw = bid - NBA;
        const int kt = (bw % (HIDDEN / 32)) * 32;
        const int nt = (bw / (HIDDEN / 32)) * 32;
        const int x = tid & 31;
        const int y = tid >> 5;            // 0..7
        const int srcRowBase = (nt < HIDDEN) ? 0 : HIDDEN;
        const int srcCol     = ((nt < HIDDEN) ? nt : nt - HIDDEN) + x;
        #pragma unroll
        for (int r = y; r < 32; r += 8)
            t[r][x] = W1[(size_t)(srcRowBase + kt + r) * HIDDEN + srcCol];
        __syncthreads();
        #pragma unroll
        for (int r = y; r < 32; r += 8)
            g_Wt[(size_t)(nt + r) * HIDDEN + kt + x] = __float2half(t[x][r]);
    } else {
        int idx = (bid - NBA - NBW) * 256 + tid;
        if (idx < EDC * HIDDEN) {
            int e = idx / HIDDEN;
            int j = idx % HIDDEN;
            float s = b1[j];
            #pragma unroll
            for (int tt = 0; tt < META; tt++)
                s += ed_table[e * META + tt] * W1[(size_t)(2 * HIDDEN + tt) * HIDDEN + j];
            g_Eh[idx] = __float2half(s);
        }
    }
}

// ---------------------------------------------------------------------------
// fp16 mma.sync GEMM: P = A @ Wt^T, fp32 accum, fp16 store.  (R9 structure —
// proven local optimum: 128x128, BK=32, 4-stage cp.async, 80B rows, 2 CTA/SM)
// ---------------------------------------------------------------------------
#define BK 32
#define NBLK (HIDDEN / BK)          // 24
#define ROWB 80
#define TILEB (128 * ROWB)          // 10240
#define STAGEB (2 * TILEB)          // 20480 (A, B)
#define STAGES 4
#define GEMM_SMEM (STAGES * STAGEB) // 81920

static __device__ __forceinline__ uint32_t smem_u32(const void* p) {
    uint32_t a;
    asm("{ .reg .u64 t; cvta.to.shared.u64 t, %1; cvt.u32.u64 %0, t; }" : "=r"(a) : "l"(p));
    return a;
}
static __device__ __forceinline__ void cp16(uint32_t dst, const void* src) {
    asm volatile("cp.async.cg.shared.global [%0], [%1], 16;" :: "r"(dst), "l"(src));
}
static __device__ __forceinline__ void ldmx4(uint32_t& r0, uint32_t& r1,
                                             uint32_t& r2, uint32_t& r3, uint32_t a) {
    asm volatile("ldmatrix.sync.aligned.m8n8.x4.shared.b16 {%0,%1,%2,%3}, [%4];"
                 : "=r"(r0), "=r"(r1), "=r"(r2), "=r"(r3) : "r"(a));
}
static __device__ __forceinline__ void mma16816(float* c, const uint32_t* a, const uint32_t* b) {
    asm volatile(
        "mma.sync.aligned.m16n8k16.row.col.f32.f16.f16.f32 "
        "{%0,%1,%2,%3}, {%4,%5,%6,%7}, {%8,%9}, {%0,%1,%2,%3};"
        : "+f"(c[0]), "+f"(c[1]), "+f"(c[2]), "+f"(c[3])
        : "r"(a[0]), "r"(a[1]), "r"(a[2]), "r"(a[3]), "r"(b[0]), "r"(b[1]));
}

__global__ __launch_bounds__(256, 2) void mma_gemm_kernel() {
    extern __shared__ char smem[];
    const uint32_t sb = smem_u32(smem);
    const int tid = threadIdx.x;
    const int lane = tid & 31;
    const int wid = tid >> 5;
    const int m0 = blockIdx.y * 128;
    const int n0 = blockIdx.x * 128;
    const int warpM = wid & 1;       // 2 warps in M
    const int warpN = wid >> 1;      // 4 warps in N

    const int ldRow = tid >> 1;      // 0..127
    const int ldSeg = (tid & 1) * 2; // 0 or 2 (16B segs)

    float acc[4][4][4];
    #pragma unroll
    for (int i = 0; i < 4; i++)
        #pragma unroll
        for (int j = 0; j < 4; j++)
            #pragma unroll
            for (int q = 0; q < 4; q++) acc[i][j][q] = 0.f;

    auto issue_load = [&](int blk) {
        const int stage = blk % STAGES;
        const __half* ga = g_Ah + (size_t)(m0 + ldRow) * HIDDEN + blk * BK + ldSeg * 8;
        const __half* gb = g_Wt + (size_t)(n0 + ldRow) * HIDDEN + blk * BK + ldSeg * 8;
        uint32_t d = sb + stage * STAGEB + ldRow * ROWB + ldSeg * 16;
        cp16(d,         ga);  cp16(d + 16,         ga + 8);
        cp16(d + TILEB, gb);  cp16(d + TILEB + 16, gb + 8);
        asm volatile("cp.async.commit_group;" ::: "memory");
    };

    issue_load(0);
    issue_load(1);
    issue_load(2);

    // precomputed intra-tile ldmatrix offsets
    const uint32_t aoff = (warpM * 64 + (lane & 15)) * ROWB + (lane >> 4) * 16;
    const int gg = lane >> 3;
    const int rr = lane & 7;
    const uint32_t boff = (warpN * 32 + ((gg >> 1) * 8 + rr)) * ROWB + (gg & 1) * 16;

    for (int blk = 0; blk < NBLK; blk++) {
        const int stage = blk % STAGES;
        asm volatile("cp.async.wait_group 2;" ::: "memory");
        __syncthreads();
        if (blk + 3 < NBLK) issue_load(blk + 3);

        const uint32_t Ab = sb + stage * STAGEB;
        const uint32_t Bb = Ab + TILEB;

        // hoist ALL fragments for this k-block (2 x k16)
        uint32_t a[2][4][4], b[2][4][2];
        #pragma unroll
        for (int ks = 0; ks < 2; ks++) {
            const int kb = ks * 32;
            #pragma unroll
            for (int nf2 = 0; nf2 < 2; nf2++)
                ldmx4(b[ks][nf2 * 2][0], b[ks][nf2 * 2][1],
                      b[ks][nf2 * 2 + 1][0], b[ks][nf2 * 2 + 1][1],
                      Bb + boff + nf2 * 16 * ROWB + kb);
            #pragma unroll
            for (int mf = 0; mf < 4; mf++)
                ldmx4(a[ks][mf][0], a[ks][mf][1], a[ks][mf][2], a[ks][mf][3],
                      Ab + aoff + mf * 16 * ROWB + kb);
        }
        #pragma unroll
        for (int ks = 0; ks < 2; ks++)
            #pragma unroll
            for (int mf = 0; mf < 4; mf++)
                #pragma unroll
                for (int nf = 0; nf < 4; nf++)
                    mma16816(acc[mf][nf], a[ks][mf], b[ks][nf]);
    }

    // store P as fp16
    #pragma unroll
    for (int mf = 0; mf < 4; mf++) {
        const int r0 = m0 + warpM * 64 + mf * 16 + (lane >> 2);
        #pragma unroll
        for (int nf = 0; nf < 4; nf++) {
            const int c = n0 + warpN * 32 + nf * 8 + (lane & 3) * 2;
            if (r0 < MROWS)
                *(__half2*)(g_Ph + (size_t)r0 * NCOLS + c) =
                    __floats2half2_rn(acc[mf][nf][0], acc[mf][nf][1]);
            if (r0 + 8 < MROWS)
                *(__half2*)(g_Ph + (size_t)(r0 + 8) * NCOLS + c) =
                    __floats2half2_rn(acc[mf][nf][2], acc[mf][nf][3]);
        }
    }
}

// ---------------------------------------------------------------------------
// Persistent epilogue: w2 in per-lane REGISTERS (no smem -> no 8-way LDS
// conflicts), half2 add/relu, fp32 dot. One warp per pair, stride loop.
// ---------------------------------------------------------------------------
#define EPI_CTAS 592

__global__ __launch_bounds__(256) void epilogue_kernel(
    const int* __restrict__ pairs, const int* __restrict__ eds,
    const float* __restrict__ W2, const float* __restrict__ b2,
    float* __restrict__ out)
{
    const int lane = threadIdx.x & 31;

    // per-lane w2 registers: element j = j0*256 + lane*8 + q*2 (+0/1)
    float2 w2r[12];
    #pragma unroll
    for (int j0 = 0; j0 < 3; j0++)
        #pragma unroll
        for (int q = 0; q < 4; q++)
            w2r[j0 * 4 + q] = *(const float2*)(W2 + j0 * 256 + lane * 8 + q * 2);

    const float bias = b2[0];
    const __half2 hzero = __float2half2_rn(0.f);

    const int gwarp = (blockIdx.x * 256 + threadIdx.x) >> 5;
    const int nwarp = (EPI_CTAS * 256) >> 5;

    for (int p = gwarp; p < TOTPAIRS; p += nwarp) {
        const int b  = (p >= NPAIRS) ? 1 : 0;
        const int i0 = pairs[(size_t)p * 2 + 0];
        const int i1 = pairs[(size_t)p * 2 + 1];
        const int e  = eds[p];

        const __half* rowA = g_Ph + (size_t)(b * NMENT + i0) * NCOLS;
        const __half* rowB = g_Ph + (size_t)(b * NMENT + i1) * NCOLS + HIDDEN;
        const __half* rowE = g_Eh + (size_t)e * HIDDEN;

        // hoisted loads: 9 independent LDG.128
        uint4 ua[3], ub[3], ue[3];
        #pragma unroll
        for (int j0 = 0; j0 < 3; j0++) {
            const int h0 = j0 * 256 + lane * 8;
            ua[j0] = *(const uint4*)(rowA + h0);
            ub[j0] = *(const uint4*)(rowB + h0);
            ue[j0] = *(const uint4*)(rowE + h0);
        }

        float acc = 0.f;
        #pragma unroll
        for (int j0 = 0; j0 < 3; j0++) {
            const __half2* ha = (const __half2*)&ua[j0];
            const __half2* hb = (const __half2*)&ub[j0];
            const __half2* he = (const __half2*)&ue[j0];
            #pragma unroll
            for (int q = 0; q < 4; q++) {
                __half2 s = __hadd2(__hadd2(ha[q], hb[q]), he[q]);
                s = __hmax2(s, hzero);
                float2 f = __half22float2(s);
                float2 w = w2r[j0 * 4 + q];
                acc = fmaf(f.x, w.x, acc);
                acc = fmaf(f.y, w.y, acc);
            }
        }
        #pragma unroll
        for (int off = 16; off; off >>= 1)
            acc += __shfl_xor_sync(0xffffffff, acc, off);
        if (lane == 0) out[p] = acc + bias;
    }
}

// ---------------------------------------------------------------------------
extern "C" void kernel_launch(void* const* d_in, const int* in_sizes, int n_in,
                              void* d_out, int out_size) {
    const float* mention_reprs = (const float*)d_in[0];
    const int*   pairs         = (const int*)d_in[1];
    const int*   eds           = (const int*)d_in[2];
    const float* ed_table      = (const float*)d_in[3];
    const float* W1            = (const float*)d_in[4];
    const float* b1            = (const float*)d_in[5];
    const float* W2            = (const float*)d_in[6];
    const float* b2            = (const float*)d_in[7];
    float* out = (float*)d_out;

    cudaFuncSetAttribute(mma_gemm_kernel,
                         cudaFuncAttributeMaxDynamicSharedMemorySize, GEMM_SMEM);

    prep_kernel<<<NB_PREP, 256>>>(mention_reprs, W1, ed_table, b1);
    { dim3 grid(NCOLS / 128, MPAD / 128);  // (12, 32)
      mma_gemm_kernel<<<grid, 256, GEMM_SMEM>>>(); }
    epilogue_kernel<<<EPI_CTAS, 256>>>(pairs, eds, W2, b2, out);
}